// round 1
// baseline (speedup 1.0000x reference)
#include <cuda_runtime.h>
#include <math.h>

#define BB 16
#define SS 8192
#define DD 256   // D_MODEL
#define CC 256   // K_CH
#define OO 256   // OUT
#define NCHUNK 64
#define ROWS_PER_CHUNK (SS / NCHUNK)   // 128

// ---------------- scratch (no allocations allowed) ----------------
__device__ __align__(16) float g_qk[BB * CC];       // Wk @ q  (per batch)
__device__ float g_qbk[BB];                         // q · bk
__device__ float g_scores[BB * SS];
__device__ float g_rmax[BB];
__device__ float g_rsuminv[BB];
__device__ __align__(16) float g_partial[BB * NCHUNK * CC];
__device__ __align__(16) float g_ctx[BB * OO];

// ---------------- K1: per-batch projections (tiny) ----------------
// q[o] = sum_d query[d]*Wq[d,o] + bq[o]
// qk[c] = sum_o Wk[c,o]*q[o]
// qbk   = sum_o q[o]*bk[o]
__global__ void k_project_q(const float* __restrict__ query,
                            const float* __restrict__ Wq,
                            const float* __restrict__ bq,
                            const float* __restrict__ Wk,
                            const float* __restrict__ bk) {
    int b = blockIdx.x, t = threadIdx.x;
    __shared__ float sq[DD];
    __shared__ float sQ[OO];
    __shared__ float red[256];

    sq[t] = query[b * DD + t];
    __syncthreads();

    float acc = bq[t];
    #pragma unroll 8
    for (int d = 0; d < DD; d++) acc += sq[d] * Wq[d * OO + t];
    sQ[t] = acc;
    __syncthreads();

    float a2 = 0.f;
    #pragma unroll 8
    for (int o = 0; o < OO; o++) a2 += Wk[t * OO + o] * sQ[o];
    g_qk[b * CC + t] = a2;

    red[t] = sQ[t] * bk[t];
    __syncthreads();
    for (int st = 128; st > 0; st >>= 1) {
        if (t < st) red[t] += red[t + st];
        __syncthreads();
    }
    if (t == 0) g_qbk[b] = red[0];
}

// ---------------- K2: scores (reads key once, 134 MB) ----------------
// One warp per key row; each lane covers 8 floats (2 x float4).
__global__ void k_scores(const float* __restrict__ key) {
    int b = blockIdx.y;
    int row0 = blockIdx.x * 64;
    int warp = threadIdx.x >> 5;
    int lane = threadIdx.x & 31;

    __shared__ __align__(16) float sqk[CC];
    sqk[threadIdx.x] = g_qk[b * CC + threadIdx.x];
    __syncthreads();
    const float4* sqk4 = (const float4*)sqk;

    float qbk = g_qbk[b];
    const float scale = 0.0625f;   // 1/sqrt(256)

    #pragma unroll
    for (int it = 0; it < 8; it++) {
        int s = row0 + it * 8 + warp;
        const float4* krow = (const float4*)(key + ((size_t)b * SS + s) * CC);
        float4 k0 = krow[lane];
        float4 k1 = krow[lane + 32];
        float4 q0 = sqk4[lane];
        float4 q1 = sqk4[lane + 32];
        float acc = k0.x * q0.x + k0.y * q0.y + k0.z * q0.z + k0.w * q0.w
                  + k1.x * q1.x + k1.y * q1.y + k1.z * q1.z + k1.w * q1.w;
        #pragma unroll
        for (int off = 16; off > 0; off >>= 1)
            acc += __shfl_down_sync(0xffffffffu, acc, off);
        if (lane == 0) g_scores[b * SS + s] = (acc + qbk) * scale;
    }
}

// ---------------- K3: per-batch softmax stats (512 KB) ----------------
__global__ void k_softmax_stats() {
    int b = blockIdx.x, t = threadIdx.x;
    __shared__ float red[256];

    float m = -1e30f;
    for (int i = t; i < SS; i += 256) m = fmaxf(m, g_scores[b * SS + i]);
    red[t] = m;
    __syncthreads();
    for (int st = 128; st > 0; st >>= 1) {
        if (t < st) red[t] = fmaxf(red[t], red[t + st]);
        __syncthreads();
    }
    float rmax = red[0];
    __syncthreads();

    float ssum = 0.f;
    for (int i = t; i < SS; i += 256) ssum += __expf(g_scores[b * SS + i] - rmax);
    red[t] = ssum;
    __syncthreads();
    for (int st = 128; st > 0; st >>= 1) {
        if (t < st) red[t] += red[t + st];
        __syncthreads();
    }
    if (t == 0) {
        g_rmax[b] = rmax;
        g_rsuminv[b] = 1.0f / red[0];
    }
}

// ---------------- K4: weighted value partial sums (reads value once, 134 MB) --
// grid (NCHUNK, B); thread c accumulates column c over ROWS_PER_CHUNK rows.
__global__ void k_weighted_value(const float* __restrict__ value) {
    int b = blockIdx.y, chunk = blockIdx.x, c = threadIdx.x;
    int s0 = chunk * ROWS_PER_CHUNK;

    __shared__ float sw[ROWS_PER_CHUNK];
    if (c < ROWS_PER_CHUNK) {
        float rmax = g_rmax[b];
        float rinv = g_rsuminv[b];
        sw[c] = __expf(g_scores[b * SS + s0 + c] - rmax) * rinv;
    }
    __syncthreads();

    const float* vbase = value + ((size_t)b * SS + s0) * CC;
    float acc = 0.f;
    #pragma unroll 4
    for (int r = 0; r < ROWS_PER_CHUNK; r++) {
        acc += sw[r] * vbase[(size_t)r * CC + c];
    }
    g_partial[((size_t)b * NCHUNK + chunk) * CC + c] = acc;
}

// ---------------- K5: reduce partials + V projection (tiny) ----------------
__global__ void k_project_ctx(const float* __restrict__ Wv,
                              const float* __restrict__ bv) {
    int b = blockIdx.x, t = threadIdx.x;
    __shared__ float scv[CC];

    float acc = 0.f;
    #pragma unroll 8
    for (int k = 0; k < NCHUNK; k++)
        acc += g_partial[((size_t)b * NCHUNK + k) * CC + t];
    scv[t] = acc;
    __syncthreads();

    float o = bv[t];
    #pragma unroll 8
    for (int c = 0; c < CC; c++) o += scv[c] * Wv[c * OO + t];
    g_ctx[b * OO + t] = o;
}

// ---------------- K6: broadcast write (134 MB) ----------------
// grid (S/128, B); block of 256 threads = 4 rows per iteration, float4 stores.
__global__ void k_broadcast(float* __restrict__ out) {
    int b = blockIdx.y;
    int s0 = blockIdx.x * 128;
    int o4 = threadIdx.x & 63;
    int sl = threadIdx.x >> 6;

    __shared__ __align__(16) float4 sctx[64];
    if (threadIdx.x < 64)
        sctx[threadIdx.x] = ((const float4*)(g_ctx + b * OO))[threadIdx.x];
    __syncthreads();

    float4 v = sctx[o4];
    float4* obase = (float4*)(out + ((size_t)b * SS + s0) * OO);
    #pragma unroll 8
    for (int it = 0; it < 32; it++) {
        obase[(size_t)(it * 4 + sl) * 64 + o4] = v;
    }
}

// ---------------- launch ----------------
extern "C" void kernel_launch(void* const* d_in, const int* in_sizes, int n_in,
                              void* d_out, int out_size) {
    const float* query = (const float*)d_in[0];
    const float* key   = (const float*)d_in[1];
    const float* value = (const float*)d_in[2];
    const float* Wq    = (const float*)d_in[3];
    const float* bq    = (const float*)d_in[4];
    const float* Wk    = (const float*)d_in[5];
    const float* bk    = (const float*)d_in[6];
    const float* Wv    = (const float*)d_in[7];
    const float* bv    = (const float*)d_in[8];
    float* out = (float*)d_out;

    k_project_q<<<BB, 256>>>(query, Wq, bq, Wk, bk);
    k_scores<<<dim3(SS / 64, BB), 256>>>(key);
    k_softmax_stats<<<BB, 256>>>();
    k_weighted_value<<<dim3(NCHUNK, BB), 256>>>(value);
    k_project_ctx<<<BB, 256>>>(Wv, bv);
    k_broadcast<<<dim3(SS / 128, BB), 256>>>(out);
}

// round 6
// speedup vs baseline: 1.1891x; 1.1891x over previous
#include <cuda_runtime.h>
#include <math.h>

#define BB 16
#define SS 8192
#define DD 256   // D_MODEL
#define CC 256   // K_CH
#define OO 256   // OUT
#define NCHUNK 64
#define ROWS_PER_CHUNK (SS / NCHUNK)   // 128
#define NSBLK (SS / 64)                // 128 score blocks per batch

// ---------------- scratch (no allocations allowed) ----------------
__device__ __align__(16) float g_qk[BB * CC];       // Wk @ q  (per batch)
__device__ float g_qbk[BB];                         // q . bk
__device__ float g_scores[BB * SS];
__device__ float g_bmax[BB * NSBLK];
__device__ float g_bsum[BB * NSBLK];
__device__ __align__(16) float g_partial[BB * NCHUNK * CC];
__device__ __align__(16) float g_ctx[BB * OO];

// ---------------- K1: per-batch projections (tiny) ----------------
__global__ void k_project_q(const float* __restrict__ query,
                            const float* __restrict__ Wq,
                            const float* __restrict__ bq,
                            const float* __restrict__ Wk,
                            const float* __restrict__ bk) {
    int b = blockIdx.x, t = threadIdx.x;
    __shared__ float sq[DD];
    __shared__ float sQ[OO];
    __shared__ float red[256];

    sq[t] = query[b * DD + t];
    __syncthreads();

    float acc = bq[t];
    #pragma unroll 8
    for (int d = 0; d < DD; d++) acc += sq[d] * Wq[d * OO + t];
    sQ[t] = acc;
    __syncthreads();

    float a2 = 0.f;
    #pragma unroll 8
    for (int o = 0; o < OO; o++) a2 += Wk[t * OO + o] * sQ[o];
    g_qk[b * CC + t] = a2;

    red[t] = sQ[t] * bk[t];
    __syncthreads();
    for (int st = 128; st > 0; st >>= 1) {
        if (t < st) red[t] += red[t + st];
        __syncthreads();
    }
    if (t == 0) g_qbk[b] = red[0];
}

// ---------------- K2: scores + per-block softmax partials ----------------
// grid (SS/64, B), block 256 = 8 warps. Each warp: 8 rows.
// Phase 1: 16 independent float4 streaming loads per thread (high MLP).
// Phase 2: 8 independent butterfly reductions (pipelined).
// Then block computes local max + sum(exp(s - localmax)) over its 64 rows.
__global__ void k_scores(const float* __restrict__ key) {
    int b = blockIdx.y;
    int blk = blockIdx.x;
    int row0 = blk * 64;
    int t = threadIdx.x;
    int warp = t >> 5;
    int lane = t & 31;

    __shared__ __align__(16) float4 sqk4[64];
    __shared__ float ssc[64];
    if (t < 64) sqk4[t] = ((const float4*)(g_qk + b * CC))[t];
    __syncthreads();

    float4 q0 = sqk4[lane];
    float4 q1 = sqk4[lane + 32];
    float qbk = g_qbk[b];

    const float4* kb = (const float4*)(key + ((size_t)b * SS + row0 + warp * 8) * CC);

    float acc[8];
    #pragma unroll
    for (int it = 0; it < 8; it++) {
        float4 k0 = __ldcs(&kb[(size_t)it * 64 + lane]);
        float4 k1 = __ldcs(&kb[(size_t)it * 64 + lane + 32]);
        acc[it] = k0.x * q0.x + k0.y * q0.y + k0.z * q0.z + k0.w * q0.w
                + k1.x * q1.x + k1.y * q1.y + k1.z * q1.z + k1.w * q1.w;
    }

    #pragma unroll
    for (int it = 0; it < 8; it++) {
        float a = acc[it];
        #pragma unroll
        for (int off = 16; off > 0; off >>= 1)
            a += __shfl_xor_sync(0xffffffffu, a, off);
        if (lane == it) ssc[warp * 8 + it] = (a + qbk) * 0.0625f;
    }
    __syncthreads();

    if (t < 64) g_scores[b * SS + row0 + t] = ssc[t];

    // block softmax partials over 64 scores (first warp only)
    if (warp == 0) {
        float s0 = ssc[lane];
        float s1 = ssc[lane + 32];
        float m = fmaxf(s0, s1);
        #pragma unroll
        for (int off = 16; off > 0; off >>= 1)
            m = fmaxf(m, __shfl_xor_sync(0xffffffffu, m, off));
        float e = __expf(s0 - m) + __expf(s1 - m);
        #pragma unroll
        for (int off = 16; off > 0; off >>= 1)
            e += __shfl_xor_sync(0xffffffffu, e, off);
        if (lane == 0) {
            g_bmax[b * NSBLK + blk] = m;
            g_bsum[b * NSBLK + blk] = e;
        }
    }
}

// ---------------- K4: weighted value partial sums (combine inlined) --------
// grid (NCHUNK, B), block 256. Each block first redundantly merges the 128
// per-block (max,sum) softmax partials (L2-resident, ~1KB) into (M, 1/Z),
// then computes its chunk's weighted-value partial with float4 streaming
// loads, 4 rows in flight.
__global__ void k_weighted_value(const float* __restrict__ value) {
    int b = blockIdx.y, chunk = blockIdx.x;
    int s0 = chunk * ROWS_PER_CHUNK;
    int t = threadIdx.x;
    int rg = t >> 6;
    int c4 = t & 63;

    __shared__ float red[128];
    __shared__ float sMZ[2];

    // --- inline log-sum-exp combine over NSBLK=128 partials ---
    float myb = 0.f;
    if (t < NSBLK) {
        myb = g_bmax[b * NSBLK + t];
        red[t] = myb;
    }
    __syncthreads();
    for (int st = 64; st > 0; st >>= 1) {
        if (t < st) red[t] = fmaxf(red[t], red[t + st]);
        __syncthreads();
    }
    float M = red[0];
    __syncthreads();
    if (t < NSBLK) red[t] = g_bsum[b * NSBLK + t] * __expf(myb - M);
    __syncthreads();
    for (int st = 64; st > 0; st >>= 1) {
        if (t < st) red[t] += red[t + st];
        __syncthreads();
    }
    if (t == 0) {
        sMZ[0] = M;
        sMZ[1] = 1.0f / red[0];
    }
    __syncthreads();
    float rmax = sMZ[0];
    float rinv = sMZ[1];

    // --- softmax weights for this chunk's 128 rows ---
    __shared__ float sw[ROWS_PER_CHUNK];
    if (t < ROWS_PER_CHUNK)
        sw[t] = __expf(g_scores[b * SS + s0 + t] - rmax) * rinv;
    __syncthreads();

    const float4* vbase = (const float4*)(value + ((size_t)b * SS + s0) * CC) + c4;

    float4 acc = make_float4(0.f, 0.f, 0.f, 0.f);
    #pragma unroll 8
    for (int i = 0; i < 32; i++) {
        int r = rg + 4 * i;
        float w = sw[r];
        float4 v = __ldcs(&vbase[(size_t)r * 64]);
        acc.x += w * v.x;
        acc.y += w * v.y;
        acc.z += w * v.z;
        acc.w += w * v.w;
    }

    __shared__ __align__(16) float4 sacc[256];
    sacc[t] = acc;
    __syncthreads();
    if (t < 64) {
        float4 a = sacc[t], b4 = sacc[t + 64], c = sacc[t + 128], d = sacc[t + 192];
        float4 r;
        r.x = (a.x + b4.x) + (c.x + d.x);
        r.y = (a.y + b4.y) + (c.y + d.y);
        r.z = (a.z + b4.z) + (c.z + d.z);
        r.w = (a.w + b4.w) + (c.w + d.w);
        ((float4*)(g_partial + ((size_t)b * NCHUNK + chunk) * CC))[t] = r;
    }
}

// ---------------- K5: reduce partials + V projection (tiny) ----------------
__global__ void k_project_ctx(const float* __restrict__ Wv,
                              const float* __restrict__ bv) {
    int b = blockIdx.x, t = threadIdx.x;
    __shared__ float scv[CC];

    float acc = 0.f;
    #pragma unroll 8
    for (int k = 0; k < NCHUNK; k++)
        acc += g_partial[((size_t)b * NCHUNK + k) * CC + t];
    scv[t] = acc;
    __syncthreads();

    float o = bv[t];
    #pragma unroll 8
    for (int c = 0; c < CC; c++) o += scv[c] * Wv[c * OO + t];
    g_ctx[b * OO + t] = o;
}

// ---------------- K6: broadcast write (134 MB, streaming stores) ----------
// grid (S/128, B), block 256 = 4 rows per iteration, float4 stores.
__global__ void k_broadcast(float* __restrict__ out) {
    int b = blockIdx.y;
    int s0 = blockIdx.x * 128;
    int o4 = threadIdx.x & 63;
    int sl = threadIdx.x >> 6;

    __shared__ __align__(16) float4 sctx[64];
    if (threadIdx.x < 64)
        sctx[threadIdx.x] = ((const float4*)(g_ctx + b * OO))[threadIdx.x];
    __syncthreads();

    float4 v = sctx[o4];
    float4* obase = (float4*)(out + ((size_t)b * SS + s0) * OO);
    #pragma unroll 8
    for (int it = 0; it < 32; it++) {
        __stcs(&obase[(size_t)(it * 4 + sl) * 64 + o4], v);
    }
}

// ---------------- launch ----------------
extern "C" void kernel_launch(void* const* d_in, const int* in_sizes, int n_in,
                              void* d_out, int out_size) {
    const float* query = (const float*)d_in[0];
    const float* key   = (const float*)d_in[1];
    const float* value = (const float*)d_in[2];
    const float* Wq    = (const float*)d_in[3];
    const float* bq    = (const float*)d_in[4];
    const float* Wk    = (const float*)d_in[5];
    const float* bk    = (const float*)d_in[6];
    const float* Wv    = (const float*)d_in[7];
    const float* bv    = (const float*)d_in[8];
    float* out = (float*)d_out;

    k_project_q<<<BB, 256>>>(query, Wq, bq, Wk, bk);
    k_scores<<<dim3(NSBLK, BB), 256>>>(key);
    k_weighted_value<<<dim3(NCHUNK, BB), 256>>>(value);
    k_project_ctx<<<BB, 256>>>(Wv, bv);
    k_broadcast<<<dim3(SS / 128, BB), 256>>>(out);
}

// round 15
// speedup vs baseline: 1.7021x; 1.4315x over previous
#include <cuda_runtime.h>
#include <math.h>

#define BB 16
#define SS 8192
#define DD 256   // D_MODEL
#define CC 256   // K_CH
#define OO 256   // OUT
#define NCHUNK 64
#define ROWS_PER_CHUNK (SS / NCHUNK)   // 128
#define NSBLK (SS / 64)                // 128 score blocks per batch

// ---------------- scratch (no allocations allowed) ----------------
__device__ __align__(16) float g_qk[BB * CC];       // Wk @ q  (per batch)
__device__ float g_qbk[BB];                         // q . bk
__device__ float g_scores[BB * SS];
__device__ float g_bmax[BB * NSBLK];
__device__ float g_bsum[BB * NSBLK];
__device__ __align__(16) float g_partial[BB * NCHUNK * CC];
__device__ __align__(16) float g_ctx[BB * OO];

// ---------------- K1: fused q projection + qk = Wk @ q ----------------
// grid (8, BB), 256 threads. Every block redundantly computes the full
// q = query@Wq + bq (coalesced Wq loads, L2-resident after first block),
// then its 32 rows of qk via warp-per-row float4 dots. Block cblk==0 also
// produces qbk = q . bk.
__global__ void k_project_qk(const float* __restrict__ query,
                             const float* __restrict__ Wq,
                             const float* __restrict__ bq,
                             const float* __restrict__ Wk,
                             const float* __restrict__ bk) {
    int b = blockIdx.y, cblk = blockIdx.x;
    int t = threadIdx.x, w = t >> 5, l = t & 31;

    __shared__ float sq[DD];
    __shared__ __align__(16) float sQ[OO];
    __shared__ float red[256];

    sq[t] = query[b * DD + t];
    __syncthreads();

    float a0 = 0.f, a1 = 0.f, a2 = 0.f, a3 = 0.f;
    #pragma unroll 8
    for (int d = 0; d < DD; d += 4) {
        a0 += sq[d + 0] * Wq[(d + 0) * OO + t];
        a1 += sq[d + 1] * Wq[(d + 1) * OO + t];
        a2 += sq[d + 2] * Wq[(d + 2) * OO + t];
        a3 += sq[d + 3] * Wq[(d + 3) * OO + t];
    }
    float q = (a0 + a1) + (a2 + a3) + bq[t];
    sQ[t] = q;

    if (cblk == 0) {
        red[t] = q * bk[t];
    }
    __syncthreads();
    if (cblk == 0) {
        for (int st = 128; st > 0; st >>= 1) {
            if (t < st) red[t] += red[t + st];
            __syncthreads();
        }
        if (t == 0) g_qbk[b] = red[0];
    }

    const float4* sQ4 = (const float4*)sQ;
    float4 q0 = sQ4[l];
    float4 q1 = sQ4[l + 32];

    int c0 = cblk * 32 + w * 4;
    const float4* base = (const float4*)(Wk + (size_t)c0 * OO);

    float4 kv[8];
    #pragma unroll
    for (int r = 0; r < 4; r++) {
        kv[2 * r + 0] = base[r * 64 + l];
        kv[2 * r + 1] = base[r * 64 + l + 32];
    }
    #pragma unroll
    for (int r = 0; r < 4; r++) {
        float4 k0 = kv[2 * r + 0], k1 = kv[2 * r + 1];
        float a = k0.x * q0.x + k0.y * q0.y + k0.z * q0.z + k0.w * q0.w
                + k1.x * q1.x + k1.y * q1.y + k1.z * q1.z + k1.w * q1.w;
        #pragma unroll
        for (int off = 16; off > 0; off >>= 1)
            a += __shfl_xor_sync(0xffffffffu, a, off);
        if (l == 0) g_qk[b * CC + c0 + r] = a;
    }
}

// ---------------- K2: scores + per-block softmax partials ----------------
__global__ void k_scores(const float* __restrict__ key) {
    int b = blockIdx.y;
    int blk = blockIdx.x;
    int row0 = blk * 64;
    int t = threadIdx.x;
    int warp = t >> 5;
    int lane = t & 31;

    __shared__ __align__(16) float4 sqk4[64];
    __shared__ float ssc[64];
    if (t < 64) sqk4[t] = ((const float4*)(g_qk + b * CC))[t];
    __syncthreads();

    float4 q0 = sqk4[lane];
    float4 q1 = sqk4[lane + 32];
    float qbk = g_qbk[b];

    const float4* kb = (const float4*)(key + ((size_t)b * SS + row0 + warp * 8) * CC);

    float acc[8];
    #pragma unroll
    for (int it = 0; it < 8; it++) {
        float4 k0 = __ldcs(&kb[(size_t)it * 64 + lane]);
        float4 k1 = __ldcs(&kb[(size_t)it * 64 + lane + 32]);
        acc[it] = k0.x * q0.x + k0.y * q0.y + k0.z * q0.z + k0.w * q0.w
                + k1.x * q1.x + k1.y * q1.y + k1.z * q1.z + k1.w * q1.w;
    }

    #pragma unroll
    for (int it = 0; it < 8; it++) {
        float a = acc[it];
        #pragma unroll
        for (int off = 16; off > 0; off >>= 1)
            a += __shfl_xor_sync(0xffffffffu, a, off);
        if (lane == it) ssc[warp * 8 + it] = (a + qbk) * 0.0625f;
    }
    __syncthreads();

    if (t < 64) g_scores[b * SS + row0 + t] = ssc[t];

    if (warp == 0) {
        float s0 = ssc[lane];
        float s1 = ssc[lane + 32];
        float m = fmaxf(s0, s1);
        #pragma unroll
        for (int off = 16; off > 0; off >>= 1)
            m = fmaxf(m, __shfl_xor_sync(0xffffffffu, m, off));
        float e = __expf(s0 - m) + __expf(s1 - m);
        #pragma unroll
        for (int off = 16; off > 0; off >>= 1)
            e += __shfl_xor_sync(0xffffffffu, e, off);
        if (lane == 0) {
            g_bmax[b * NSBLK + blk] = m;
            g_bsum[b * NSBLK + blk] = e;
        }
    }
}

// ---------------- K4: weighted value partial sums (combine inlined) --------
__global__ void k_weighted_value(const float* __restrict__ value) {
    int b = blockIdx.y, chunk = blockIdx.x;
    int s0 = chunk * ROWS_PER_CHUNK;
    int t = threadIdx.x;
    int rg = t >> 6;
    int c4 = t & 63;

    __shared__ float red[128];
    __shared__ float sMZ[2];

    float myb = 0.f;
    if (t < NSBLK) {
        myb = g_bmax[b * NSBLK + t];
        red[t] = myb;
    }
    __syncthreads();
    for (int st = 64; st > 0; st >>= 1) {
        if (t < st) red[t] = fmaxf(red[t], red[t + st]);
        __syncthreads();
    }
    float M = red[0];
    __syncthreads();
    if (t < NSBLK) red[t] = g_bsum[b * NSBLK + t] * __expf(myb - M);
    __syncthreads();
    for (int st = 64; st > 0; st >>= 1) {
        if (t < st) red[t] += red[t + st];
        __syncthreads();
    }
    if (t == 0) {
        sMZ[0] = M;
        sMZ[1] = 1.0f / red[0];
    }
    __syncthreads();
    float rmax = sMZ[0];
    float rinv = sMZ[1];

    __shared__ float sw[ROWS_PER_CHUNK];
    if (t < ROWS_PER_CHUNK)
        sw[t] = __expf(g_scores[b * SS + s0 + t] - rmax) * rinv;
    __syncthreads();

    const float4* vbase = (const float4*)(value + ((size_t)b * SS + s0) * CC) + c4;

    float4 acc = make_float4(0.f, 0.f, 0.f, 0.f);
    #pragma unroll 8
    for (int i = 0; i < 32; i++) {
        int r = rg + 4 * i;
        float w = sw[r];
        float4 v = __ldcs(&vbase[(size_t)r * 64]);
        acc.x += w * v.x;
        acc.y += w * v.y;
        acc.z += w * v.z;
        acc.w += w * v.w;
    }

    __shared__ __align__(16) float4 sacc[256];
    sacc[t] = acc;
    __syncthreads();
    if (t < 64) {
        float4 a = sacc[t], b4 = sacc[t + 64], c = sacc[t + 128], d = sacc[t + 192];
        float4 r;
        r.x = (a.x + b4.x) + (c.x + d.x);
        r.y = (a.y + b4.y) + (c.y + d.y);
        r.z = (a.z + b4.z) + (c.z + d.z);
        r.w = (a.w + b4.w) + (c.w + d.w);
        ((float4*)(g_partial + ((size_t)b * NCHUNK + chunk) * CC))[t] = r;
    }
}

// ---------------- K5: reduce partials + V projection (grid (8, BB)) -------
__global__ void k_project_ctx(const float* __restrict__ Wv,
                              const float* __restrict__ bv) {
    int b = blockIdx.y, oblk = blockIdx.x;
    int t = threadIdx.x;

    __shared__ float scv[CC];
    {
        const float* p = g_partial + (size_t)b * NCHUNK * CC + t;
        float s0 = 0.f, s1 = 0.f, s2 = 0.f, s3 = 0.f;
        #pragma unroll 4
        for (int k = 0; k < NCHUNK; k += 4) {
            s0 += p[(k + 0) * CC];
            s1 += p[(k + 1) * CC];
            s2 += p[(k + 2) * CC];
            s3 += p[(k + 3) * CC];
        }
        scv[t] = (s0 + s1) + (s2 + s3);
    }
    __syncthreads();

    int o = oblk * 32 + (t & 31);
    int pp = t >> 5;
    float a = 0.f;
    #pragma unroll 8
    for (int i = 0; i < 32; i++) {
        int c = pp * 32 + i;
        a += scv[c] * Wv[c * OO + o];
    }

    __shared__ float sred[256];
    sred[t] = a;
    __syncthreads();
    if (t < 32) {
        float r = sred[t] + sred[t + 32] + sred[t + 64] + sred[t + 96]
                + sred[t + 128] + sred[t + 160] + sred[t + 192] + sred[t + 224];
        g_ctx[b * OO + oblk * 32 + t] = r + bv[oblk * 32 + t];
    }
}

// ---------------- K6: broadcast write (134 MB, streaming stores) ----------
__global__ void k_broadcast(float* __restrict__ out) {
    int b = blockIdx.y;
    int s0 = blockIdx.x * 128;
    int o4 = threadIdx.x & 63;
    int sl = threadIdx.x >> 6;

    __shared__ __align__(16) float4 sctx[64];
    if (threadIdx.x < 64)
        sctx[threadIdx.x] = ((const float4*)(g_ctx + b * OO))[threadIdx.x];
    __syncthreads();

    float4 v = sctx[o4];
    float4* obase = (float4*)(out + ((size_t)b * SS + s0) * OO);
    #pragma unroll 8
    for (int it = 0; it < 32; it++) {
        __stcs(&obase[(size_t)(it * 4 + sl) * 64 + o4], v);
    }
}

// ---------------- launch ----------------
extern "C" void kernel_launch(void* const* d_in, const int* in_sizes, int n_in,
                              void* d_out, int out_size) {
    const float* query = (const float*)d_in[0];
    const float* key   = (const float*)d_in[1];
    const float* value = (const float*)d_in[2];
    const float* Wq    = (const float*)d_in[3];
    const float* bq    = (const float*)d_in[4];
    const float* Wk    = (const float*)d_in[5];
    const float* bk    = (const float*)d_in[6];
    const float* Wv    = (const float*)d_in[7];
    const float* bv    = (const float*)d_in[8];
    float* out = (float*)d_out;

    k_project_qk<<<dim3(8, BB), 256>>>(query, Wq, bq, Wk, bk);
    k_scores<<<dim3(NSBLK, BB), 256>>>(key);
    k_weighted_value<<<dim3(NCHUNK, BB), 256>>>(value);
    k_project_ctx<<<dim3(8, BB), 256>>>(Wv, bv);
    k_broadcast<<<dim3(SS / 128, BB), 256>>>(out);
}